// round 1
// baseline (speedup 1.0000x reference)
#include <cuda_runtime.h>
#include <math_constants.h>

// Problem constants
#define BS 128
#define SP_IN 256
#define SP_OUT 256
#define DN_IN 128
#define DN_OUT 128
#define N_STK 32
#define N_PNT 32
#define COOR 32
#define M_CTR 16
#define KNN_K 2

#define BN_SCALE 0.9999950000374997f   // 1/sqrt(1+1e-5)

// Scratch (device globals -- no allocation allowed)
__device__ int   g_fps[BS * M_CTR];
__device__ int   g_knn[BS * M_CTR * KNN_K];
__device__ float g_H [BS * 512 * N_STK];            // sparse GEMM result [b][512][32]
__device__ float g_Gs[BS * DN_OUT * 512];           // dense GEMM  [b][o][s*16+p]
__device__ float g_d4[BS * DN_OUT * M_CTR * 32];    // pre-conv activations [b][o][m][p]

__device__ __forceinline__ float gelu_exact(float x) {
    return 0.5f * x * (1.0f + erff(x * 0.70710678118654752f));
}
__device__ __forceinline__ float bn_gelu(float x, float g, float beta) {
    return gelu_exact(fmaf(g, x * BN_SCALE, beta));
}

// ---------------------------------------------------------------------------
// Kernel A: FPS + kNN + coor_out.  One warp per batch.
// ---------------------------------------------------------------------------
__global__ __launch_bounds__(32) void k_fps_knn(const float* __restrict__ coor,
                                                float* __restrict__ coor_out) {
    int b = blockIdx.x;
    int t = threadIdx.x;           // = point index
    __shared__ float cs[N_STK][COOR + 1];
    __shared__ float sq[N_STK];
    __shared__ int   fpsi[M_CTR];

    for (int c = 0; c < COOR; c++) cs[t][c] = coor[(b * N_STK + t) * COOR + c];
    float s = 0.f;
    for (int c = 0; c < COOR; c++) { float v = cs[t][c]; s += v * v; }
    sq[t] = s;
    __syncthreads();

    // FPS (deterministic start at 0, argmax tie -> lowest index)
    float dist = CUDART_INF_F;
    int far = 0;
    for (int it = 0; it < M_CTR; it++) {
        if (t == 0) fpsi[it] = far;
        float d = 0.f;
        #pragma unroll
        for (int c = 0; c < COOR; c++) { float df = cs[t][c] - cs[far][c]; d += df * df; }
        dist = fminf(dist, d);
        float bv = dist; int bi = t;
        #pragma unroll
        for (int o = 16; o > 0; o >>= 1) {
            float ov = __shfl_xor_sync(0xffffffffu, bv, o);
            int   oi = __shfl_xor_sync(0xffffffffu, bi, o);
            if (ov > bv || (ov == bv && oi < bi)) { bv = ov; bi = oi; }
        }
        far = bi;
    }
    __syncthreads();

    // coor_out [b, m, COOR]
    for (int m = 0; m < M_CTR; m++) {
        int r = fpsi[m];
        coor_out[(b * M_CTR + m) * COOR + t] = cs[r][t];
    }
    // kNN(k=2) for each center (smallest distance, tie -> lowest index)
    for (int m = 0; m < M_CTR; m++) {
        int ctr = fpsi[m];
        float dot = 0.f;
        #pragma unroll
        for (int c = 0; c < COOR; c++) dot += cs[ctr][c] * cs[t][c];
        float d = sq[ctr] + sq[t] - 2.0f * dot;
        float bv = d; int bi = t;
        #pragma unroll
        for (int o = 16; o > 0; o >>= 1) {
            float ov = __shfl_xor_sync(0xffffffffu, bv, o);
            int   oi = __shfl_xor_sync(0xffffffffu, bi, o);
            if (ov < bv || (ov == bv && oi < bi)) { bv = ov; bi = oi; }
        }
        int i1 = bi;
        float d2 = (t == i1) ? CUDART_INF_F : d;
        float cv = d2; int ci = t;
        #pragma unroll
        for (int o = 16; o > 0; o >>= 1) {
            float ov = __shfl_xor_sync(0xffffffffu, cv, o);
            int   oi = __shfl_xor_sync(0xffffffffu, ci, o);
            if (ov < cv || (ov == cv && oi < ci)) { cv = ov; ci = oi; }
        }
        if (t == 0) {
            g_knn[(b * M_CTR + m) * 2 + 0] = i1;
            g_knn[(b * M_CTR + m) * 2 + 1] = ci;
        }
    }
    if (t < M_CTR) g_fps[b * M_CTR + t] = fpsi[t];
}

// ---------------------------------------------------------------------------
// Kernel B: sparse GEMM  H[b][o'][s] ;  o'<256 -> Wa row, o'>=256 -> Wc row
// grid (4, BS), block 256
// ---------------------------------------------------------------------------
__global__ __launch_bounds__(256) void k_sparse_gemm(const float* __restrict__ sf,
                                                     const float* __restrict__ sp_w) {
    int b = blockIdx.y, og = blockIdx.x;
    __shared__ __align__(16) float s_sf[SP_IN * N_STK];   // 32KB
    int t = threadIdx.x;
    for (int j = 0; j < 32; j++) s_sf[j * 256 + t] = sf[b * (SP_IN * N_STK) + j * 256 + t];
    __syncthreads();

    int o_loc = t >> 1;
    int c0 = (t & 1) * 16;
    int op = og * 128 + o_loc;
    const float* wp = (op < 256) ? (sp_w + op * 512) : (sp_w + (op - 256) * 512 + 256);

    float acc[16];
    #pragma unroll
    for (int j = 0; j < 16; j++) acc[j] = 0.f;

    #pragma unroll 4
    for (int i = 0; i < 256; i++) {
        float w = __ldg(wp + i);
        const float4* v = reinterpret_cast<const float4*>(&s_sf[i * 32 + c0]);
        float4 v0 = v[0], v1 = v[1], v2 = v[2], v3 = v[3];
        acc[0]  = fmaf(w, v0.x, acc[0]);  acc[1]  = fmaf(w, v0.y, acc[1]);
        acc[2]  = fmaf(w, v0.z, acc[2]);  acc[3]  = fmaf(w, v0.w, acc[3]);
        acc[4]  = fmaf(w, v1.x, acc[4]);  acc[5]  = fmaf(w, v1.y, acc[5]);
        acc[6]  = fmaf(w, v1.z, acc[6]);  acc[7]  = fmaf(w, v1.w, acc[7]);
        acc[8]  = fmaf(w, v2.x, acc[8]);  acc[9]  = fmaf(w, v2.y, acc[9]);
        acc[10] = fmaf(w, v2.z, acc[10]); acc[11] = fmaf(w, v2.w, acc[11]);
        acc[12] = fmaf(w, v3.x, acc[12]); acc[13] = fmaf(w, v3.y, acc[13]);
        acc[14] = fmaf(w, v3.z, acc[14]); acc[15] = fmaf(w, v3.w, acc[15]);
    }
    float* Ho = g_H + (b * 512 + op) * 32 + c0;
    float4* Ho4 = reinterpret_cast<float4*>(Ho);
    Ho4[0] = make_float4(acc[0], acc[1], acc[2], acc[3]);
    Ho4[1] = make_float4(acc[4], acc[5], acc[6], acc[7]);
    Ho4[2] = make_float4(acc[8], acc[9], acc[10], acc[11]);
    Ho4[3] = make_float4(acc[12], acc[13], acc[14], acc[15]);
}

// ---------------------------------------------------------------------------
// Kernel B2: sparse epilogue -> sparse_out [b, o, m]
// ---------------------------------------------------------------------------
__global__ __launch_bounds__(256) void k_sparse_epi(const float* __restrict__ sp_b,
                                                    const float* __restrict__ sp_g,
                                                    const float* __restrict__ sp_beta,
                                                    float* __restrict__ out_sp) {
    int tid = blockIdx.x * 256 + threadIdx.x;
    if (tid >= BS * SP_OUT * M_CTR) return;
    int m = tid & 15;
    int o = (tid >> 4) & 255;
    int b = tid >> 12;
    int ctr = g_fps[b * M_CTR + m];
    int n0 = g_knn[(b * M_CTR + m) * 2 + 0];
    int n1 = g_knn[(b * M_CTR + m) * 2 + 1];
    const float* Ha = g_H + (b * 512 + o) * 32;
    const float* Hc = g_H + (b * 512 + 256 + o) * 32;
    float base = -Ha[ctr] + Hc[ctr] + sp_b[o];
    float gg = sp_g[o], bt = sp_beta[o];
    float a0 = bn_gelu(Ha[n0] + base, gg, bt);
    float a1 = bn_gelu(Ha[n1] + base, gg, bt);
    out_sp[tid] = fmaxf(a0, a1);
}

// ---------------------------------------------------------------------------
// Kernel C: dense GEMM  Gs[b][o][s*16+p] = sum_c W[o,c]*fea[c,s,2p] + W[o,c+128]*fea[c,s,2p+1]
// M=128, N=512/batch (tiles of 64), K=256.  grid (8, BS), block 256 (16x16, 8x4 micro)
// ---------------------------------------------------------------------------
#define KC 16
__global__ __launch_bounds__(256) void k_dense_gemm(const float* __restrict__ dense,
                                                    const float* __restrict__ dn_w) {
    int b = blockIdx.y, g = blockIdx.x;    // g: strokes [g*4, g*4+4)
    __shared__ __align__(16) float As[KC][128];
    __shared__ __align__(16) float Bs[KC][64];
    int t = threadIdx.x;
    int tm = t >> 4, tn = t & 15;
    const float* feab = dense + (size_t)b * DN_IN * N_STK * N_PNT;

    float acc[8][4];
    #pragma unroll
    for (int r = 0; r < 8; r++)
        #pragma unroll
        for (int c = 0; c < 4; c++) acc[r][c] = 0.f;

    for (int k0 = 0; k0 < 256; k0 += KC) {
        #pragma unroll
        for (int j = 0; j < 8; j++) {
            int idx = t * 8 + j;
            int kk = idx & 15, o = idx >> 4;
            As[kk][o] = dn_w[o * 256 + k0 + kk];
        }
        #pragma unroll
        for (int j = 0; j < 4; j++) {
            int idx = j * 256 + t;
            int kk = idx >> 6, n = idx & 63;
            int k = k0 + kk;
            int c = (k < 128) ? k : (k - 128);
            int par = (k < 128) ? 0 : 1;
            int s = g * 4 + (n >> 4), p = n & 15;
            Bs[kk][n] = feab[(c * 32 + s) * 32 + 2 * p + par];
        }
        __syncthreads();
        #pragma unroll
        for (int kk = 0; kk < KC; kk++) {
            float4 a0 = *reinterpret_cast<const float4*>(&As[kk][tm * 8]);
            float4 a1 = *reinterpret_cast<const float4*>(&As[kk][tm * 8 + 4]);
            float4 bv = *reinterpret_cast<const float4*>(&Bs[kk][tn * 4]);
            float av[8] = {a0.x, a0.y, a0.z, a0.w, a1.x, a1.y, a1.z, a1.w};
            float bb[4] = {bv.x, bv.y, bv.z, bv.w};
            #pragma unroll
            for (int r = 0; r < 8; r++)
                #pragma unroll
                for (int c = 0; c < 4; c++) acc[r][c] = fmaf(av[r], bb[c], acc[r][c]);
        }
        __syncthreads();
    }
    #pragma unroll
    for (int r = 0; r < 8; r++) {
        int o = tm * 8 + r;
        float4 v = make_float4(acc[r][0], acc[r][1], acc[r][2], acc[r][3]);
        *reinterpret_cast<float4*>(&g_Gs[(b * 128 + o) * 512 + g * 64 + tn * 4]) = v;
    }
}

// ---------------------------------------------------------------------------
// Kernel D: d4[b][i][m][p]  (pre-conv activations, max over k)
// ---------------------------------------------------------------------------
__global__ __launch_bounds__(256) void k_d4(const float* __restrict__ dn_b,
                                            const float* __restrict__ dn_g,
                                            const float* __restrict__ dn_beta) {
    int tid = blockIdx.x * 256 + threadIdx.x;
    if (tid >= BS * DN_OUT * M_CTR * 32) return;
    int p = tid & 31;
    int m = (tid >> 5) & 15;
    int i = (tid >> 9) & 127;
    int b = tid >> 16;
    int ctr = g_fps[b * M_CTR + m];
    const float* Grow = g_Gs + (b * 128 + i) * 512;
    float bb = dn_b[i], gg = dn_g[i], bt = dn_beta[i];
    float v;
    if (p < 16) {
        int n0 = g_knn[(b * M_CTR + m) * 2 + 0];
        int n1 = g_knn[(b * M_CTR + m) * 2 + 1];
        float gc = Grow[ctr * 16 + p];
        float x0 = Grow[n0 * 16 + p] - gc + bb;
        float x1 = Grow[n1 * 16 + p] - gc + bb;
        v = fmaxf(bn_gelu(x0, gg, bt), bn_gelu(x1, gg, bt));
    } else {
        v = bn_gelu(Grow[ctr * 16 + (p - 16)] + bb, gg, bt);
    }
    g_d4[tid] = v;
}

// ---------------------------------------------------------------------------
// Kernel E2: conv (1x3, stride 2 on W, pad 1) as implicit GEMM, M=128 (o),
// N=256 (m*w) per batch (tiles of 64), K=384 (i*3+tt).  grid (4, BS)
// ---------------------------------------------------------------------------
__global__ __launch_bounds__(256) void k_conv(const float* __restrict__ ds_w,
                                              const float* __restrict__ ds_b,
                                              const float* __restrict__ ds_g,
                                              const float* __restrict__ ds_beta,
                                              float* __restrict__ out_dn) {
    int b = blockIdx.y, g = blockIdx.x;    // g: n-tile [g*64, g*64+64)
    __shared__ __align__(16) float As[KC][128];
    __shared__ __align__(16) float Bs[KC][64];
    int t = threadIdx.x;
    int tm = t >> 4, tn = t & 15;
    const float* d4b = g_d4 + (size_t)b * 128 * 16 * 32;

    float acc[8][4];
    #pragma unroll
    for (int r = 0; r < 8; r++)
        #pragma unroll
        for (int c = 0; c < 4; c++) acc[r][c] = 0.f;

    for (int k0 = 0; k0 < 384; k0 += KC) {
        #pragma unroll
        for (int j = 0; j < 8; j++) {
            int idx = t * 8 + j;
            int kk = idx & 15, o = idx >> 4;
            As[kk][o] = ds_w[o * 384 + k0 + kk];
        }
        #pragma unroll
        for (int j = 0; j < 4; j++) {
            int idx = j * 256 + t;
            int kk = idx >> 6, n = idx & 63;
            int k = k0 + kk;
            int i = k / 3, tt = k - 3 * i;
            int nn = g * 64 + n;
            int m = nn >> 4, w = nn & 15;
            int x = 2 * w - 1 + tt;
            float v = 0.f;
            if (x >= 0 && x < 32) v = d4b[(i * 16 + m) * 32 + x];
            Bs[kk][n] = v;
        }
        __syncthreads();
        #pragma unroll
        for (int kk = 0; kk < KC; kk++) {
            float4 a0 = *reinterpret_cast<const float4*>(&As[kk][tm * 8]);
            float4 a1 = *reinterpret_cast<const float4*>(&As[kk][tm * 8 + 4]);
            float4 bv = *reinterpret_cast<const float4*>(&Bs[kk][tn * 4]);
            float av[8] = {a0.x, a0.y, a0.z, a0.w, a1.x, a1.y, a1.z, a1.w};
            float bb[4] = {bv.x, bv.y, bv.z, bv.w};
            #pragma unroll
            for (int r = 0; r < 8; r++)
                #pragma unroll
                for (int c = 0; c < 4; c++) acc[r][c] = fmaf(av[r], bb[c], acc[r][c]);
        }
        __syncthreads();
    }
    #pragma unroll
    for (int r = 0; r < 8; r++) {
        int o = tm * 8 + r;
        float bbias = ds_b[o], gg = ds_g[o], bt = ds_beta[o];
        #pragma unroll
        for (int c = 0; c < 4; c++) {
            int nn = g * 64 + tn * 4 + c;
            int m = nn >> 4, w = nn & 15;
            float y = bn_gelu(acc[r][c] + bbias, gg, bt);
            out_dn[((b * 128 + o) * 16 + m) * 16 + w] = y;
        }
    }
}

// ---------------------------------------------------------------------------
extern "C" void kernel_launch(void* const* d_in, const int* in_sizes, int n_in,
                              void* d_out, int out_size) {
    const float* sparse_fea = (const float*)d_in[0];
    const float* dense_fea  = (const float*)d_in[1];
    const float* stk_coor   = (const float*)d_in[2];
    int base = 3;
    if (n_in >= 16 && in_sizes[3] == 1) base = 4;  // skip n_stk_center scalar
    const float* sp_w    = (const float*)d_in[base + 0];
    const float* sp_b    = (const float*)d_in[base + 1];
    const float* sp_g    = (const float*)d_in[base + 2];
    const float* sp_beta = (const float*)d_in[base + 3];
    const float* dn_w    = (const float*)d_in[base + 4];
    const float* dn_b    = (const float*)d_in[base + 5];
    const float* dn_g    = (const float*)d_in[base + 6];
    const float* dn_beta = (const float*)d_in[base + 7];
    const float* ds_w    = (const float*)d_in[base + 8];
    const float* ds_b    = (const float*)d_in[base + 9];
    const float* ds_g    = (const float*)d_in[base + 10];
    const float* ds_beta = (const float*)d_in[base + 11];

    float* out = (float*)d_out;
    float* out_sparse = out;                                  // [128,256,16]
    float* out_dense  = out + BS * SP_OUT * M_CTR;            // [128,128,16,16]
    float* out_coor   = out_dense + BS * DN_OUT * M_CTR * 16; // [128,16,32]

    k_fps_knn<<<BS, 32>>>(stk_coor, out_coor);
    k_sparse_gemm<<<dim3(4, BS), 256>>>(sparse_fea, sp_w);
    k_dense_gemm<<<dim3(8, BS), 256>>>(dense_fea, dn_w);
    k_sparse_epi<<<(BS * SP_OUT * M_CTR + 255) / 256, 256>>>(sp_b, sp_g, sp_beta, out_sparse);
    k_d4<<<(BS * DN_OUT * M_CTR * 32 + 255) / 256, 256>>>(dn_b, dn_g, dn_beta);
    k_conv<<<dim3(4, BS), 256>>>(ds_w, ds_b, ds_g, ds_beta, out_dense);
}

// round 3
// speedup vs baseline: 2.0017x; 2.0017x over previous
#include <cuda_runtime.h>
#include <math_constants.h>
#include <cstdint>

#define BS 128
#define M_CTR 16
#define BN_SCALE 0.9999950000374997f

// ---------------- scratch ----------------
__device__ int   g_fps[BS * M_CTR];
__device__ int   g_knn[BS * M_CTR * 2];
__device__ float g_Xs [4096 * 256];            // sparse B  [n=b*32+s][c]
__device__ float g_HT [4096 * 512];            // sparse C  [n][op]
__device__ float g_GsT[65536 * 128];           // dense  C  [n=b*512+s*16+p][o]
__device__ float g_d4m[BS * 16 * 32 * 128];    // d4        [b][m][x][i]

// ---------------- helpers ----------------
__device__ __forceinline__ float gelu_exact(float x) {
    return 0.5f * x * (1.0f + erff(x * 0.70710678118654752f));
}
__device__ __forceinline__ float bn_gelu(float x, float g, float beta) {
    return gelu_exact(fmaf(g, x * BN_SCALE, beta));
}
__device__ __forceinline__ uint32_t f2tf(float f) {
    uint32_t o;
    asm("cvt.rna.tf32.f32 %0, %1;" : "=r"(o) : "f"(f));
    return o;
}
__device__ __forceinline__ void mma_tf32(float* d, const uint32_t* a, const uint32_t* b) {
    asm volatile(
        "mma.sync.aligned.m16n8k8.row.col.f32.tf32.tf32.f32 "
        "{%0,%1,%2,%3}, {%4,%5,%6,%7}, {%8,%9}, {%0,%1,%2,%3};\n"
        : "+f"(d[0]), "+f"(d[1]), "+f"(d[2]), "+f"(d[3])
        : "r"(a[0]), "r"(a[1]), "r"(a[2]), "r"(a[3]), "r"(b[0]), "r"(b[1]));
}

// ---------------------------------------------------------------------------
// FPS + kNN + coor_out.  One warp per batch. (exact f32, matches reference)
// ---------------------------------------------------------------------------
__global__ __launch_bounds__(32) void k_fps_knn(const float* __restrict__ coor,
                                                float* __restrict__ coor_out) {
    int b = blockIdx.x;
    int t = threadIdx.x;
    __shared__ float cs[32][33];
    __shared__ float sq[32];
    __shared__ int   fpsi[M_CTR];

    for (int c = 0; c < 32; c++) cs[t][c] = coor[(b * 32 + t) * 32 + c];
    float s = 0.f;
    for (int c = 0; c < 32; c++) { float v = cs[t][c]; s += v * v; }
    sq[t] = s;
    __syncthreads();

    float dist = CUDART_INF_F;
    int far = 0;
    for (int it = 0; it < M_CTR; it++) {
        if (t == 0) fpsi[it] = far;
        float d = 0.f;
        #pragma unroll
        for (int c = 0; c < 32; c++) { float df = cs[t][c] - cs[far][c]; d += df * df; }
        dist = fminf(dist, d);
        float bv = dist; int bi = t;
        #pragma unroll
        for (int o = 16; o > 0; o >>= 1) {
            float ov = __shfl_xor_sync(0xffffffffu, bv, o);
            int   oi = __shfl_xor_sync(0xffffffffu, bi, o);
            if (ov > bv || (ov == bv && oi < bi)) { bv = ov; bi = oi; }
        }
        far = bi;
    }
    __syncthreads();

    for (int m = 0; m < M_CTR; m++) {
        int r = fpsi[m];
        coor_out[(b * M_CTR + m) * 32 + t] = cs[r][t];
    }
    for (int m = 0; m < M_CTR; m++) {
        int ctr = fpsi[m];
        float dot = 0.f;
        #pragma unroll
        for (int c = 0; c < 32; c++) dot += cs[ctr][c] * cs[t][c];
        float d = sq[ctr] + sq[t] - 2.0f * dot;
        float bv = d; int bi = t;
        #pragma unroll
        for (int o = 16; o > 0; o >>= 1) {
            float ov = __shfl_xor_sync(0xffffffffu, bv, o);
            int   oi = __shfl_xor_sync(0xffffffffu, bi, o);
            if (ov < bv || (ov == bv && oi < bi)) { bv = ov; bi = oi; }
        }
        int i1 = bi;
        float d2 = (t == i1) ? CUDART_INF_F : d;
        float cv = d2; int ci = t;
        #pragma unroll
        for (int o = 16; o > 0; o >>= 1) {
            float ov = __shfl_xor_sync(0xffffffffu, cv, o);
            int   oi = __shfl_xor_sync(0xffffffffu, ci, o);
            if (ov < cv || (ov == cv && oi < ci)) { cv = ov; ci = oi; }
        }
        if (t == 0) {
            g_knn[(b * M_CTR + m) * 2 + 0] = i1;
            g_knn[(b * M_CTR + m) * 2 + 1] = ci;
        }
    }
    if (t < M_CTR) g_fps[b * M_CTR + t] = fpsi[t];
}

// ---------------------------------------------------------------------------
// pack_Xs: Xs[(b*32+s)][c] = sf[b][c][s]
// ---------------------------------------------------------------------------
__global__ __launch_bounds__(256) void pack_Xs(const float* __restrict__ sf) {
    int b = blockIdx.x, t = threadIdx.x;
    __shared__ float ts[256][33];
    const float* src = sf + ((size_t)b * 256 + t) * 32;
    #pragma unroll
    for (int j = 0; j < 8; j++) {
        float4 v = reinterpret_cast<const float4*>(src)[j];
        ts[t][j * 4 + 0] = v.x; ts[t][j * 4 + 1] = v.y;
        ts[t][j * 4 + 2] = v.z; ts[t][j * 4 + 3] = v.w;
    }
    __syncthreads();
    int s = t >> 3;
    float4* dst = reinterpret_cast<float4*>(g_Xs) + ((size_t)b * 32 + s) * 64;
    #pragma unroll
    for (int j = 0; j < 8; j++) {
        int k4 = (t & 7) + j * 8;
        int c0 = k4 * 4;
        dst[k4] = make_float4(ts[c0][s], ts[c0 + 1][s], ts[c0 + 2][s], ts[c0 + 3][s]);
    }
}

// ---------------------------------------------------------------------------
// Warp-mma tf32 GEMM. Block tile M=128, N=64; 8 warps (4M x 2N) of 32x32.
// MODE 0: sparse  C[op][n]  A=sp_w(split) [512x256], B=g_Xs,  out g_HT[n][op]
// MODE 1: dense   C[o][n]   A=dn_w [128x256], B=im2col(dense_fea), out g_GsT[n][o]
// MODE 2: conv    C[o][n]   A=ds_w taps [128x384], B=gather(g_d4m), out=bn_gelu->Cout
// ---------------------------------------------------------------------------
#define A_STR 20
#define B_STR 68

template <int MODE>
__global__ __launch_bounds__(256) void gemm_ws(const float* __restrict__ A0,
                                               const float* __restrict__ B0,
                                               const float* __restrict__ eb,
                                               const float* __restrict__ eg,
                                               const float* __restrict__ ebt,
                                               float* __restrict__ Cout) {
    __shared__ union {
        struct { uint32_t A[128 * A_STR]; uint32_t B[16 * B_STR]; } t;
        float Cs[128 * 65];
    } su;

    const int t = threadIdx.x;
    const int lane = t & 31;
    const int wid = t >> 5;
    const int g = lane >> 2, t4 = lane & 3;
    const int wm = wid & 3, wn = wid >> 2;

    // mode-specific block mapping
    int n0 = 0;             // MODE 0: global n base
    size_t aoff0 = 0;       // MODE 0: A base offset
    int opTile = 0;
    int bb = 0, s0 = 0, ng = 0, sg = 0;
    if (MODE == 0) {
        n0 = blockIdx.x * 64;
        opTile = blockIdx.y * 128;
        aoff0 = (blockIdx.y < 2) ? (size_t)opTile * 512
                                 : (size_t)(opTile - 256) * 512 + 256;
    } else if (MODE == 1) {
        bb = blockIdx.x >> 3; sg = blockIdx.x & 7; s0 = sg * 4;
    } else {
        bb = blockIdx.x >> 2; ng = blockIdx.x & 3;
    }

    float d[2][4][4];
    #pragma unroll
    for (int mt = 0; mt < 2; mt++)
        #pragma unroll
        for (int nt = 0; nt < 4; nt++)
            #pragma unroll
            for (int e = 0; e < 4; e++) d[mt][nt][e] = 0.f;

    const int NCH = (MODE == 2) ? 24 : 16;

    for (int ch = 0; ch < NCH; ch++) {
        int k0 = ch * 16;
        // ---- A tile fill: 128 x 16 ----
        #pragma unroll
        for (int j = 0; j < 8; j++) {
            int idx = j * 256 + t;
            int kk = idx & 15, m = idx >> 4;
            float v;
            if (MODE == 0) {
                v = A0[aoff0 + (size_t)m * 512 + k0 + kk];
            } else if (MODE == 1) {
                v = A0[m * 256 + k0 + kk];
            } else {
                int tap = k0 >> 7, i0 = k0 & 127;
                v = A0[m * 384 + (i0 + kk) * 3 + tap];
            }
            su.t.A[m * A_STR + kk] = f2tf(v);
        }
        // ---- B tile fill: 16 x 64 ----
        #pragma unroll
        for (int j = 0; j < 4; j++) {
            int idx = j * 256 + t;
            float v; int kk, n;
            if (MODE == 0) {
                kk = idx & 15; n = idx >> 4;
                v = g_Xs[(size_t)(n0 + n) * 256 + k0 + kk];
            } else if (MODE == 1) {
                n = idx & 63; kk = idx >> 6;
                int k = k0 + kk;
                int c = k & 127, par = k >> 7;
                int s = s0 + (n >> 4), p = n & 15;
                v = __ldg(&B0[(((size_t)bb * 128 + c) * 32 + s) * 32 + 2 * p + par]);
            } else {
                kk = idx & 15; n = idx >> 4;
                int tap = k0 >> 7, i0 = k0 & 127;
                int m = ng * 4 + (n >> 4), w = n & 15;
                int x = 2 * w - 1 + tap;
                v = (x >= 0 && x < 32)
                        ? g_d4m[(((size_t)bb * 16 + m) * 32 + x) * 128 + i0 + kk]
                        : 0.f;
            }
            su.t.B[kk * B_STR + n] = f2tf(v);
        }
        __syncthreads();
        // ---- compute: 2 k-steps of 8 ----
        #pragma unroll
        for (int ks = 0; ks < 2; ks++) {
            int ko = ks * 8;
            uint32_t a[2][4], b[4][2];
            #pragma unroll
            for (int mt = 0; mt < 2; mt++) {
                int r = wm * 32 + mt * 16 + g;
                a[mt][0] = su.t.A[r * A_STR + ko + t4];
                a[mt][1] = su.t.A[(r + 8) * A_STR + ko + t4];
                a[mt][2] = su.t.A[r * A_STR + ko + t4 + 4];
                a[mt][3] = su.t.A[(r + 8) * A_STR + ko + t4 + 4];
            }
            #pragma unroll
            for (int nt = 0; nt < 4; nt++) {
                int cn = wn * 32 + nt * 8 + g;
                b[nt][0] = su.t.B[(ko + t4) * B_STR + cn];
                b[nt][1] = su.t.B[(ko + t4 + 4) * B_STR + cn];
            }
            #pragma unroll
            for (int mt = 0; mt < 2; mt++)
                #pragma unroll
                for (int nt = 0; nt < 4; nt++)
                    mma_tf32(d[mt][nt], a[mt], b[nt]);
        }
        __syncthreads();
    }

    if (MODE < 2) {
        // transpose C through smem -> coalesced [n][o] stores
        #pragma unroll
        for (int mt = 0; mt < 2; mt++)
            #pragma unroll
            for (int nt = 0; nt < 4; nt++)
                #pragma unroll
                for (int e = 0; e < 4; e++) {
                    int m = wm * 32 + mt * 16 + g + ((e & 2) ? 8 : 0);
                    int n = wn * 32 + nt * 8 + 2 * t4 + (e & 1);
                    su.Cs[m * 65 + n] = d[mt][nt][e];
                }
        __syncthreads();
        #pragma unroll
        for (int j = 0; j < 32; j++) {
            int idx = j * 256 + t;
            int o = idx & 127, n = idx >> 7;
            float v = su.Cs[o * 65 + n];
            if (MODE == 0)
                g_HT[(size_t)(n0 + n) * 512 + opTile + o] = v;
            else
                g_GsT[((size_t)bb * 512 + sg * 64 + n) * 128 + o] = v;
        }
    } else {
        // conv epilogue: bias + BN + GELU, write out_dense[b][o][m][w]
        #pragma unroll
        for (int mt = 0; mt < 2; mt++) {
            int o_lo = wm * 32 + mt * 16 + g;
            int o_hi = o_lo + 8;
            float b_lo = eb[o_lo], g_lo = eg[o_lo], t_lo = ebt[o_lo];
            float b_hi = eb[o_hi], g_hi = eg[o_hi], t_hi = ebt[o_hi];
            #pragma unroll
            for (int nt = 0; nt < 4; nt++) {
                int n = ng * 64 + wn * 32 + nt * 8 + 2 * t4;
                float2 v0, v1;
                v0.x = bn_gelu(d[mt][nt][0] + b_lo, g_lo, t_lo);
                v0.y = bn_gelu(d[mt][nt][1] + b_lo, g_lo, t_lo);
                v1.x = bn_gelu(d[mt][nt][2] + b_hi, g_hi, t_hi);
                v1.y = bn_gelu(d[mt][nt][3] + b_hi, g_hi, t_hi);
                *reinterpret_cast<float2*>(&Cout[((size_t)bb * 128 + o_lo) * 256 + n]) = v0;
                *reinterpret_cast<float2*>(&Cout[((size_t)bb * 128 + o_hi) * 256 + n]) = v1;
            }
        }
    }
}

// ---------------------------------------------------------------------------
// sparse epilogue: out_sp[b][o][m]
// ---------------------------------------------------------------------------
__global__ __launch_bounds__(256) void k_sparse_epi(const float* __restrict__ sp_b,
                                                    const float* __restrict__ sp_g,
                                                    const float* __restrict__ sp_beta,
                                                    float* __restrict__ out_sp) {
    int tid = blockIdx.x * 256 + threadIdx.x;
    int o = tid & 255;
    int m = (tid >> 8) & 15;
    int b = tid >> 12;
    int ctr = g_fps[b * M_CTR + m];
    int i0 = g_knn[(b * M_CTR + m) * 2 + 0];
    int i1 = g_knn[(b * M_CTR + m) * 2 + 1];
    const float* Hc = g_HT + (size_t)(b * 32 + ctr) * 512;
    float base = -Hc[o] + Hc[256 + o] + sp_b[o];
    float gg = sp_g[o], bt = sp_beta[o];
    float a0 = bn_gelu(g_HT[(size_t)(b * 32 + i0) * 512 + o] + base, gg, bt);
    float a1 = bn_gelu(g_HT[(size_t)(b * 32 + i1) * 512 + o] + base, gg, bt);
    out_sp[(size_t)b * 4096 + o * 16 + m] = fmaxf(a0, a1);
}

// ---------------------------------------------------------------------------
// d4: g_d4m[b][m][x][i]
// ---------------------------------------------------------------------------
__global__ __launch_bounds__(256) void k_d4(const float* __restrict__ dn_b,
                                            const float* __restrict__ dn_g,
                                            const float* __restrict__ dn_beta) {
    int tid = blockIdx.x * 256 + threadIdx.x;
    int i = tid & 127;
    int p = (tid >> 7) & 31;
    int m = (tid >> 12) & 15;
    int b = tid >> 16;
    int ctr = g_fps[b * M_CTR + m];
    float bb = dn_b[i], gg = dn_g[i], bt = dn_beta[i];
    float v;
    if (p < 16) {
        int i0 = g_knn[(b * M_CTR + m) * 2 + 0];
        int i1 = g_knn[(b * M_CTR + m) * 2 + 1];
        float gc = g_GsT[(size_t)(b * 512 + ctr * 16 + p) * 128 + i];
        float x0 = g_GsT[(size_t)(b * 512 + i0 * 16 + p) * 128 + i] - gc + bb;
        float x1 = g_GsT[(size_t)(b * 512 + i1 * 16 + p) * 128 + i] - gc + bb;
        v = fmaxf(bn_gelu(x0, gg, bt), bn_gelu(x1, gg, bt));
    } else {
        float gc = g_GsT[(size_t)(b * 512 + ctr * 16 + (p - 16)) * 128 + i];
        v = bn_gelu(gc + bb, gg, bt);
    }
    g_d4m[(((size_t)b * 16 + m) * 32 + p) * 128 + i] = v;
}

// ---------------------------------------------------------------------------
extern "C" void kernel_launch(void* const* d_in, const int* in_sizes, int n_in,
                              void* d_out, int out_size) {
    const float* sparse_fea = (const float*)d_in[0];
    const float* dense_fea  = (const float*)d_in[1];
    const float* stk_coor   = (const float*)d_in[2];
    int base = 3;
    if (n_in >= 16 && in_sizes[3] == 1) base = 4;
    const float* sp_w    = (const float*)d_in[base + 0];
    const float* sp_b    = (const float*)d_in[base + 1];
    const float* sp_g    = (const float*)d_in[base + 2];
    const float* sp_beta = (const float*)d_in[base + 3];
    const float* dn_w    = (const float*)d_in[base + 4];
    const float* dn_b    = (const float*)d_in[base + 5];
    const float* dn_g    = (const float*)d_in[base + 6];
    const float* dn_beta = (const float*)d_in[base + 7];
    const float* ds_w    = (const float*)d_in[base + 8];
    const float* ds_b    = (const float*)d_in[base + 9];
    const float* ds_g    = (const float*)d_in[base + 10];
    const float* ds_beta = (const float*)d_in[base + 11];

    float* out = (float*)d_out;
    float* out_sparse = out;
    float* out_dense  = out + BS * 256 * M_CTR;
    float* out_coor   = out_dense + BS * 128 * M_CTR * 16;

    k_fps_knn<<<BS, 32>>>(stk_coor, out_coor);
    pack_Xs<<<BS, 256>>>(sparse_fea);
    gemm_ws<0><<<dim3(64, 4), 256>>>(sp_w, nullptr, nullptr, nullptr, nullptr, nullptr);
    k_sparse_epi<<<2048, 256>>>(sp_b, sp_g, sp_beta, out_sparse);
    gemm_ws<1><<<1024, 256>>>(dn_w, dense_fea, nullptr, nullptr, nullptr, nullptr);
    k_d4<<<32768, 256>>>(dn_b, dn_g, dn_beta);
    gemm_ws<2><<<512, 256>>>(ds_w, nullptr, ds_b, ds_g, ds_beta, out_dense);
}

// round 4
// speedup vs baseline: 2.3180x; 1.1580x over previous
#include <cuda_runtime.h>
#include <math_constants.h>
#include <cstdint>

#define BS 128
#define M_CTR 16
#define BN_SCALE 0.9999950000374997f

// ---------------- scratch ----------------
__device__ int   g_fps[BS * M_CTR];
__device__ int   g_knn[BS * M_CTR * 2];
__device__ float g_GsT[65536 * 128];           // dense  C  [n=b*512+s*16+p][o]
__device__ float g_d4m[BS * 16 * 32 * 128];    // d4        [b][m][x][i]

// ---------------- helpers ----------------
__device__ __forceinline__ float gelu_exact(float x) {
    return 0.5f * x * (1.0f + erff(x * 0.70710678118654752f));
}
__device__ __forceinline__ float bn_gelu(float x, float g, float beta) {
    return gelu_exact(fmaf(g, x * BN_SCALE, beta));
}
__device__ __forceinline__ uint32_t f2tf(float f) {
    uint32_t o;
    asm("cvt.rna.tf32.f32 %0, %1;" : "=r"(o) : "f"(f));
    return o;
}
__device__ __forceinline__ void mma_tf32(float* d, const uint32_t* a, const uint32_t* b) {
    asm volatile(
        "mma.sync.aligned.m16n8k8.row.col.f32.tf32.tf32.f32 "
        "{%0,%1,%2,%3}, {%4,%5,%6,%7}, {%8,%9}, {%0,%1,%2,%3};\n"
        : "+f"(d[0]), "+f"(d[1]), "+f"(d[2]), "+f"(d[3])
        : "r"(a[0]), "r"(a[1]), "r"(a[2]), "r"(a[3]), "r"(b[0]), "r"(b[1]));
}

// ---------------------------------------------------------------------------
// FPS + kNN + coor_out.  One warp per batch. (exact f32, matches reference)
// ---------------------------------------------------------------------------
__global__ __launch_bounds__(32) void k_fps_knn(const float* __restrict__ coor,
                                                float* __restrict__ coor_out) {
    int b = blockIdx.x;
    int t = threadIdx.x;
    __shared__ float cs[32][33];
    __shared__ float sq[32];
    __shared__ int   fpsi[M_CTR];

    for (int c = 0; c < 32; c++) cs[t][c] = coor[(b * 32 + t) * 32 + c];
    float s = 0.f;
    for (int c = 0; c < 32; c++) { float v = cs[t][c]; s += v * v; }
    sq[t] = s;
    __syncthreads();

    float dist = CUDART_INF_F;
    int far = 0;
    for (int it = 0; it < M_CTR; it++) {
        if (t == 0) fpsi[it] = far;
        float d = 0.f;
        #pragma unroll
        for (int c = 0; c < 32; c++) { float df = cs[t][c] - cs[far][c]; d += df * df; }
        dist = fminf(dist, d);
        float bv = dist; int bi = t;
        #pragma unroll
        for (int o = 16; o > 0; o >>= 1) {
            float ov = __shfl_xor_sync(0xffffffffu, bv, o);
            int   oi = __shfl_xor_sync(0xffffffffu, bi, o);
            if (ov > bv || (ov == bv && oi < bi)) { bv = ov; bi = oi; }
        }
        far = bi;
    }
    __syncthreads();

    for (int m = 0; m < M_CTR; m++) {
        int r = fpsi[m];
        coor_out[(b * M_CTR + m) * 32 + t] = cs[r][t];
    }
    for (int m = 0; m < M_CTR; m++) {
        int ctr = fpsi[m];
        float dot = 0.f;
        #pragma unroll
        for (int c = 0; c < 32; c++) dot += cs[ctr][c] * cs[t][c];
        float d = sq[ctr] + sq[t] - 2.0f * dot;
        float bv = d; int bi = t;
        #pragma unroll
        for (int o = 16; o > 0; o >>= 1) {
            float ov = __shfl_xor_sync(0xffffffffu, bv, o);
            int   oi = __shfl_xor_sync(0xffffffffu, bi, o);
            if (ov < bv || (ov == bv && oi < bi)) { bv = ov; bi = oi; }
        }
        int i1 = bi;
        float d2 = (t == i1) ? CUDART_INF_F : d;
        float cv = d2; int ci = t;
        #pragma unroll
        for (int o = 16; o > 0; o >>= 1) {
            float ov = __shfl_xor_sync(0xffffffffu, cv, o);
            int   oi = __shfl_xor_sync(0xffffffffu, ci, o);
            if (ov < cv || (ov == cv && oi < ci)) { cv = ov; ci = oi; }
        }
        if (t == 0) {
            g_knn[(b * M_CTR + m) * 2 + 0] = i1;
            g_knn[(b * M_CTR + m) * 2 + 1] = ci;
        }
    }
    if (t < M_CTR) g_fps[b * M_CTR + t] = fpsi[t];
}

// ---------------------------------------------------------------------------
// Pipelined warp-mma tf32 GEMM. Block tile M=128, N=64; 8 warps (4Mx2N) of 32x32.
// Double-buffered smem, register prefetch, 1 sync per 16-K chunk.
// MODE 0: sparse. A rows: m<64 -> Wa[oT+m], m>=64 -> Wc[oT+m-64].  B read
//         directly from sparse_fea (N-tile = 2 whole batches).  FUSED sparse
//         epilogue (BN+GELU+max over kNN) via C-tile in smem -> out_sparse.
// MODE 1: dense.  A=dn_w [128x256], B=im2col(dense_fea), C -> g_GsT[n][o].
// MODE 2: conv.   A=ds_w taps [128x384], B=gather(g_d4m), C=bn_gelu -> out.
// ---------------------------------------------------------------------------
#define A_STR 20
#define B_STR 68

template <int MODE>
__global__ __launch_bounds__(256) void gemm_ws(const float* __restrict__ A0,
                                               const float* __restrict__ B0,
                                               const float* __restrict__ eb,
                                               const float* __restrict__ eg,
                                               const float* __restrict__ ebt,
                                               float* __restrict__ Cout) {
    __shared__ union {
        struct { uint32_t A[2][128 * A_STR]; uint32_t B[2][16 * B_STR]; } t;
        float Cs[128 * 65];
    } su;

    const int t = threadIdx.x;
    const int lane = t & 31;
    const int wid = t >> 5;
    const int g = lane >> 2, t4 = lane & 3;
    const int wm = wid & 3, wn = wid >> 2;

    // block mapping
    int n0 = 0, b0 = 0, oT = 0;
    int bb = 0, s0 = 0, ng = 0, sg = 0;
    if (MODE == 0) {
        n0 = blockIdx.x * 64;          // 2 whole batches
        b0 = blockIdx.x * 2;
        oT = blockIdx.y * 64;
    } else if (MODE == 1) {
        bb = blockIdx.x >> 3; sg = blockIdx.x & 7; s0 = sg * 4;
    } else {
        bb = blockIdx.x >> 2; ng = blockIdx.x & 3;
    }

    const int NCH = (MODE == 2) ? 24 : 16;
    float ra[8], rb[4];

    // ---- global load of chunk ch into registers ----
    auto loadA = [&](int ch) {
        int k0 = ch * 16;
        #pragma unroll
        for (int j = 0; j < 8; j++) {
            int idx = j * 256 + t;
            int kk = idx & 15, m = idx >> 4;
            if (MODE == 0) {
                int o = oT + (m & 63);
                ra[j] = __ldg(&A0[(size_t)o * 512 + ((m < 64) ? 0 : 256) + k0 + kk]);
            } else if (MODE == 1) {
                ra[j] = __ldg(&A0[m * 256 + k0 + kk]);
            } else {
                int tap = k0 >> 7, i0 = k0 & 127;
                ra[j] = __ldg(&A0[m * 384 + (i0 + kk) * 3 + tap]);
            }
        }
    };
    auto loadB = [&](int ch) {
        int k0 = ch * 16;
        #pragma unroll
        for (int j = 0; j < 4; j++) {
            int idx = j * 256 + t;
            if (MODE == 0) {
                int n = idx & 63, kk = idx >> 6;
                int b = b0 + (n >> 5), s = n & 31;
                rb[j] = __ldg(&B0[((size_t)b * 256 + k0 + kk) * 32 + s]);
            } else if (MODE == 1) {
                int n = idx & 63, kk = idx >> 6;
                int k = k0 + kk;
                int c = k & 127, par = k >> 7;
                int s = s0 + (n >> 4), p = n & 15;
                rb[j] = __ldg(&B0[(((size_t)bb * 128 + c) * 32 + s) * 32 + 2 * p + par]);
            } else {
                int kk = idx & 15, n = idx >> 4;
                int tap = k0 >> 7, i0 = k0 & 127;
                int m = ng * 4 + (n >> 4), w = n & 15;
                int x = 2 * w - 1 + tap;
                rb[j] = (x >= 0 && x < 32)
                            ? g_d4m[(((size_t)bb * 16 + m) * 32 + x) * 128 + i0 + kk]
                            : 0.f;
            }
        }
    };
    auto storeA = [&](int buf) {
        #pragma unroll
        for (int j = 0; j < 8; j++) {
            int idx = j * 256 + t;
            int kk = idx & 15, m = idx >> 4;
            su.t.A[buf][m * A_STR + kk] = f2tf(ra[j]);
        }
    };
    auto storeB = [&](int buf) {
        #pragma unroll
        for (int j = 0; j < 4; j++) {
            int idx = j * 256 + t;
            int kk, n;
            if (MODE == 2) { kk = idx & 15; n = idx >> 4; }
            else           { n = idx & 63;  kk = idx >> 6; }
            su.t.B[buf][kk * B_STR + n] = f2tf(rb[j]);
        }
    };

    float d[2][4][4];
    #pragma unroll
    for (int mt = 0; mt < 2; mt++)
        #pragma unroll
        for (int nt = 0; nt < 4; nt++)
            #pragma unroll
            for (int e = 0; e < 4; e++) d[mt][nt][e] = 0.f;

    // prologue
    loadA(0); loadB(0);
    storeA(0); storeB(0);
    __syncthreads();

    for (int ch = 0; ch < NCH; ch++) {
        int buf = ch & 1;
        if (ch + 1 < NCH) { loadA(ch + 1); loadB(ch + 1); }
        const uint32_t* As = su.t.A[buf];
        const uint32_t* Bs = su.t.B[buf];
        #pragma unroll
        for (int ks = 0; ks < 2; ks++) {
            int ko = ks * 8;
            uint32_t a[2][4], bfr[4][2];
            #pragma unroll
            for (int mt = 0; mt < 2; mt++) {
                int r = wm * 32 + mt * 16 + g;
                a[mt][0] = As[r * A_STR + ko + t4];
                a[mt][1] = As[(r + 8) * A_STR + ko + t4];
                a[mt][2] = As[r * A_STR + ko + t4 + 4];
                a[mt][3] = As[(r + 8) * A_STR + ko + t4 + 4];
            }
            #pragma unroll
            for (int nt = 0; nt < 4; nt++) {
                int cn = wn * 32 + nt * 8 + g;
                bfr[nt][0] = Bs[(ko + t4) * B_STR + cn];
                bfr[nt][1] = Bs[(ko + t4 + 4) * B_STR + cn];
            }
            #pragma unroll
            for (int mt = 0; mt < 2; mt++)
                #pragma unroll
                for (int nt = 0; nt < 4; nt++)
                    mma_tf32(d[mt][nt], a[mt], bfr[nt]);
        }
        if (ch + 1 < NCH) { storeA(1 - buf); storeB(1 - buf); }
        __syncthreads();
    }

    if (MODE < 2) {
        // C tile -> smem (rows = M index, cols = n)
        #pragma unroll
        for (int mt = 0; mt < 2; mt++)
            #pragma unroll
            for (int nt = 0; nt < 4; nt++)
                #pragma unroll
                for (int e = 0; e < 4; e++) {
                    int m = wm * 32 + mt * 16 + g + ((e & 2) ? 8 : 0);
                    int n = wn * 32 + nt * 8 + 2 * t4 + (e & 1);
                    su.Cs[m * 65 + n] = d[mt][nt][e];
                }
        __syncthreads();
        if (MODE == 0) {
            // fused sparse epilogue: rows 0..63 = Ha[oT+r], rows 64..127 = Hc[oT+r]
            #pragma unroll
            for (int j = 0; j < 8; j++) {
                int idx = j * 256 + t;            // < 2048
                int mm = idx & 15;
                int o_loc = (idx >> 4) & 63;
                int bl = idx >> 10;               // 0..1
                int b = b0 + bl;
                int cb = bl * 32;
                int ctr = g_fps[b * M_CTR + mm];
                int i0 = g_knn[(b * M_CTR + mm) * 2 + 0];
                int i1 = g_knn[(b * M_CTR + mm) * 2 + 1];
                float Ha_c = su.Cs[o_loc * 65 + cb + ctr];
                float Hc_c = su.Cs[(64 + o_loc) * 65 + cb + ctr];
                float Ha0  = su.Cs[o_loc * 65 + cb + i0];
                float Ha1  = su.Cs[o_loc * 65 + cb + i1];
                int o = oT + o_loc;
                float base = -Ha_c + Hc_c + eb[o];
                float gg = eg[o], bt = ebt[o];
                float r = fmaxf(bn_gelu(Ha0 + base, gg, bt), bn_gelu(Ha1 + base, gg, bt));
                Cout[(size_t)b * 4096 + o * 16 + mm] = r;
            }
        } else {
            #pragma unroll
            for (int j = 0; j < 32; j++) {
                int idx = j * 256 + t;
                int o = idx & 127, n = idx >> 7;
                g_GsT[((size_t)bb * 512 + sg * 64 + n) * 128 + o] = su.Cs[o * 65 + n];
            }
        }
    } else {
        // conv epilogue: bias + BN + GELU, write out_dense[b][o][m][w]
        #pragma unroll
        for (int mt = 0; mt < 2; mt++) {
            int o_lo = wm * 32 + mt * 16 + g;
            int o_hi = o_lo + 8;
            float b_lo = eb[o_lo], g_lo = eg[o_lo], t_lo = ebt[o_lo];
            float b_hi = eb[o_hi], g_hi = eg[o_hi], t_hi = ebt[o_hi];
            #pragma unroll
            for (int nt = 0; nt < 4; nt++) {
                int n = ng * 64 + wn * 32 + nt * 8 + 2 * t4;
                float2 v0, v1;
                v0.x = bn_gelu(d[mt][nt][0] + b_lo, g_lo, t_lo);
                v0.y = bn_gelu(d[mt][nt][1] + b_lo, g_lo, t_lo);
                v1.x = bn_gelu(d[mt][nt][2] + b_hi, g_hi, t_hi);
                v1.y = bn_gelu(d[mt][nt][3] + b_hi, g_hi, t_hi);
                *reinterpret_cast<float2*>(&Cout[((size_t)bb * 128 + o_lo) * 256 + n]) = v0;
                *reinterpret_cast<float2*>(&Cout[((size_t)bb * 128 + o_hi) * 256 + n]) = v1;
            }
        }
    }
}

// ---------------------------------------------------------------------------
// d4: g_d4m[b][m][x][i]
// ---------------------------------------------------------------------------
__global__ __launch_bounds__(256) void k_d4(const float* __restrict__ dn_b,
                                            const float* __restrict__ dn_g,
                                            const float* __restrict__ dn_beta) {
    int tid = blockIdx.x * 256 + threadIdx.x;
    int i = tid & 127;
    int p = (tid >> 7) & 31;
    int m = (tid >> 12) & 15;
    int b = tid >> 16;
    int ctr = g_fps[b * M_CTR + m];
    float bb = dn_b[i], gg = dn_g[i], bt = dn_beta[i];
    float v;
    if (p < 16) {
        int i0 = g_knn[(b * M_CTR + m) * 2 + 0];
        int i1 = g_knn[(b * M_CTR + m) * 2 + 1];
        float gc = g_GsT[(size_t)(b * 512 + ctr * 16 + p) * 128 + i];
        float x0 = g_GsT[(size_t)(b * 512 + i0 * 16 + p) * 128 + i] - gc + bb;
        float x1 = g_GsT[(size_t)(b * 512 + i1 * 16 + p) * 128 + i] - gc + bb;
        v = fmaxf(bn_gelu(x0, gg, bt), bn_gelu(x1, gg, bt));
    } else {
        float gc = g_GsT[(size_t)(b * 512 + ctr * 16 + (p - 16)) * 128 + i];
        v = bn_gelu(gc + bb, gg, bt);
    }
    g_d4m[(((size_t)b * 16 + m) * 32 + p) * 128 + i] = v;
}

// ---------------------------------------------------------------------------
extern "C" void kernel_launch(void* const* d_in, const int* in_sizes, int n_in,
                              void* d_out, int out_size) {
    const float* sparse_fea = (const float*)d_in[0];
    const float* dense_fea  = (const float*)d_in[1];
    const float* stk_coor   = (const float*)d_in[2];
    int base = 3;
    if (n_in >= 16 && in_sizes[3] == 1) base = 4;
    const float* sp_w    = (const float*)d_in[base + 0];
    const float* sp_b    = (const float*)d_in[base + 1];
    const float* sp_g    = (const float*)d_in[base + 2];
    const float* sp_beta = (const float*)d_in[base + 3];
    const float* dn_w    = (const float*)d_in[base + 4];
    const float* dn_b    = (const float*)d_in[base + 5];
    const float* dn_g    = (const float*)d_in[base + 6];
    const float* dn_beta = (const float*)d_in[base + 7];
    const float* ds_w    = (const float*)d_in[base + 8];
    const float* ds_b    = (const float*)d_in[base + 9];
    const float* ds_g    = (const float*)d_in[base + 10];
    const float* ds_beta = (const float*)d_in[base + 11];

    float* out = (float*)d_out;
    float* out_sparse = out;
    float* out_dense  = out + BS * 256 * M_CTR;
    float* out_coor   = out_dense + BS * 128 * M_CTR * 16;

    k_fps_knn<<<BS, 32>>>(stk_coor, out_coor);
    gemm_ws<0><<<dim3(64, 4), 256>>>(sp_w, sparse_fea, sp_b, sp_g, sp_beta, out_sparse);
    gemm_ws<1><<<1024, 256>>>(dn_w, dense_fea, nullptr, nullptr, nullptr, nullptr);
    k_d4<<<32768, 256>>>(dn_b, dn_g, dn_beta);
    gemm_ws<2><<<512, 256>>>(ds_w, nullptr, ds_b, ds_g, ds_beta, out_dense);
}